// round 11
// baseline (speedup 1.0000x reference)
#include <cuda_runtime.h>
#include <cuda_bf16.h>
#include <stdint.h>

#define T_STEPS 5
#define LH 128
#define NNV 16000
#define NCTA2 250        // 16000/64

// ---------------- scratch (device globals; no runtime allocation) ----------------
__device__ float d_deg [NNV];
__device__ float d_dinv[NNV];
__device__ float d_acc [NNV*T_STEPS];
__device__ __nv_bfloat16 d_y0b [(size_t)T_STEPS*NNV*LH];   // layer-0 hidden sequence
__device__ __nv_bfloat16 d_hAb [(size_t)NNV*LH];           // final layer-1 h
__device__ __nv_bfloat16 d_img0[512*200];                  // layer0 weight image [j][k], pitch 200
__device__ __nv_bfloat16 d_img1[512*264];                  // layer1, pitch 264
__device__ float d_biasC[1024];                            // [layer][u*4+gate]

// ---------------- helpers ----------------
__device__ __forceinline__ float tanhfast(float x) {
    float y; asm("tanh.approx.f32 %0, %1;" : "=f"(y) : "f"(x)); return y;
}
__device__ __forceinline__ float sigmfast(float x) { return fmaf(tanhfast(0.5f*x), 0.5f, 0.5f); }

__device__ __forceinline__ uint32_t smem_u32(const void* p) {
    uint32_t a;
    asm("{ .reg .u64 t; cvta.to.shared.u64 t, %1; cvt.u32.u64 %0, t; }" : "=r"(a) : "l"(p));
    return a;
}
__device__ __forceinline__ void cp16(uint32_t d, const void* s) {
    asm volatile("cp.async.cg.shared.global [%0], [%1], 16;" :: "r"(d), "l"(s));
}
__device__ __forceinline__ void sts128(uint32_t a, uint4 v) {
    asm volatile("st.shared.v4.b32 [%0], {%1,%2,%3,%4};" :: "r"(a), "r"(v.x), "r"(v.y), "r"(v.z), "r"(v.w) : "memory");
}
__device__ __forceinline__ void ldsm4(uint32_t a, uint32_t& r0, uint32_t& r1, uint32_t& r2, uint32_t& r3) {
    asm volatile("ldmatrix.sync.aligned.m8n8.x4.shared.b16 {%0,%1,%2,%3}, [%4];"
                 : "=r"(r0), "=r"(r1), "=r"(r2), "=r"(r3) : "r"(a));
}
__device__ __forceinline__ void mma16816(float* d, const uint32_t* a, const uint32_t* b) {
    asm volatile("mma.sync.aligned.m16n8k16.row.col.f32.bf16.bf16.f32 "
        "{%0,%1,%2,%3}, {%4,%5,%6,%7}, {%8,%9}, {%0,%1,%2,%3};"
        : "+f"(d[0]), "+f"(d[1]), "+f"(d[2]), "+f"(d[3])
        : "r"(a[0]), "r"(a[1]), "r"(a[2]), "r"(a[3]), "r"(b[0]), "r"(b[1]));
}

// ---------------- GCN scalar pipeline (4-edge ILP) ----------------
__global__ void k_deg_edges(const int* __restrict__ dst, float* deg, int E) {
    int e0 = (blockIdx.x*blockDim.x + threadIdx.x)*4;
#pragma unroll
    for (int j = 0; j < 4; j++) {
        int e = e0 + j;
        if (e < E) atomicAdd(&deg[dst[e]], 1.0f);
    }
}
__global__ void k_dinv_accinit(const float* __restrict__ x, const float* __restrict__ deg,
                               float* __restrict__ dinv, float* __restrict__ acc, int n) {
    int i = blockIdx.x*blockDim.x + threadIdx.x;
    if (i >= n) return;
    float di = rsqrtf(deg[i]);
    dinv[i] = di;
#pragma unroll
    for (int t = 0; t < T_STEPS; t++)
        acc[i*T_STEPS + t] = x[i*T_STEPS + t] * di;
}
__global__ void k_scatter(const int* __restrict__ src, const int* __restrict__ dst,
                          const float* __restrict__ x, const float* __restrict__ dinv,
                          float* __restrict__ acc, int E) {
    int e0 = (blockIdx.x*blockDim.x + threadIdx.x)*4;
#pragma unroll
    for (int j = 0; j < 4; j++) {
        int e = e0 + j;
        if (e < E) {
            int s = src[e], d = dst[e];
            float ds = dinv[s];
#pragma unroll
            for (int t = 0; t < T_STEPS; t++)
                atomicAdd(&acc[d*T_STEPS + t], x[s*T_STEPS + t] * ds);
        }
    }
}

// ---------------- weight/bias pre-transform (both layers, one launch) ----------------
__global__ void k_prepw(const float* __restrict__ Wih0, const float* __restrict__ Whh0,
                        const float* __restrict__ Wih1, const float* __restrict__ Whh1,
                        const float* __restrict__ bi0, const float* __restrict__ bh0,
                        const float* __restrict__ bi1, const float* __restrict__ bh1,
                        float* deg, int nn) {
    int gid = blockIdx.x*256 + threadIdx.x;
    if (gid < nn) deg[gid] = 1.0f;
    if (gid < 1024) {
        int l = gid >> 9, r = gid & 511;
        int u = r >> 2, gt = r & 3;
        d_biasC[gid] = l ? (bi1[gt*LH + u] + bh1[gt*LH + u])
                         : (bi0[gt*LH + u] + bh0[gt*LH + u]);
    }
    const int W0 = 512*192;
    if (gid < W0) {
        int k = gid % 192, j = gid / 192;
        int u = j >> 2, gt = j & 3;
        float v = (k < 64) ? Wih0[(gt*LH + u)*64 + k] : Whh0[(gt*LH + u)*LH + (k - 64)];
        d_img0[j*200 + k] = __float2bfloat16(v);
    } else if (gid < W0 + 512*256) {
        int g2 = gid - W0;
        int k = g2 % 256, j = g2 / 256;
        int u = j >> 2, gt = j & 3;
        float v = (k < 128) ? Wih1[(gt*LH + u)*LH + k] : Whh1[(gt*LH + u)*LH + (k - 128)];
        d_img1[j*264 + k] = __float2bfloat16(v);
    }
}

// smem layout (bytes), sized for worst case (layer1, KP=264)
#define OFF_A    0          // 64 x KP bf16     (max 33792)
#define OFF_C    33792      // 64 x 129 fp32    (33024)
#define OFF_B    66816      // 2 x 32 x KP bf16 (max 33792)
#define OFF_BIAS 100608     // 512 fp32
#define OFF_GW   102656     // 128 fp32
#define SMB_TOT  103168

// ---------------- one LSTM layer for this CTA's 64 rows (all 5 steps) -------------
// 4 warps: 2 row-groups x 2 col-halves. B streamed in 32-col double-buffered
// chunks. h lives in the A-tile h-columns; c in smem; A frags register-resident.
template<int LAYER>
__device__ __forceinline__ void run_layer(char* smem, uint32_t sb,
                                          const float* gw, const float* gb, int m0s)
{
    constexpr int KIH  = LAYER ? 128 : 64;
    constexpr int KP   = KIH + LH + 8;          // 264 / 200
    constexpr int NK16 = (KIH + LH) / 16;       // 16 / 12
    constexpr int BCH  = 32*KP*2;               // 16896 / 12800

    float* cS    = (float*)(smem + OFF_C);
    float* sbias = (float*)(smem + OFF_BIAS);
    float* sgw   = (float*)(smem + OFF_GW);

    const int tid = threadIdx.x, wid = tid >> 5, lane = tid & 31;
    const int g = lane >> 3, lr = lane & 7;
    const int wr = wid >> 1, wc = wid & 1;
    const __nv_bfloat16* img = LAYER ? d_img1 : d_img0;

    // zero A tile (h cols = 0) and c; stage bias (+gw for layer0)
    for (int i = tid; i < 33792/16; i += 128) ((uint4*)(smem + OFF_A))[i] = make_uint4(0,0,0,0);
    for (int i = tid; i < 33024/16; i += 128) ((uint4*)(smem + OFF_C))[i] = make_uint4(0,0,0,0);
    if (LAYER == 0 && tid < 128) sgw[tid] = (tid < 64) ? gw[tid] : gb[tid - 64];
    for (int i = tid; i < 512; i += 128) sbias[i] = d_biasC[LAYER*512 + i];
    __syncthreads();

    auto stage_ih = [&](int t) {
        if (LAYER == 0) {
#pragma unroll
            for (int it = 0; it < 4; it++) {            // feat cols 0..63 in-register
                int idx = tid + it*128;
                int row = idx >> 3, ch = idx & 7;
                int m = m0s + row;
                float av = d_acc[m*T_STEPS + t] * d_dinv[m];
                uint32_t w[4];
#pragma unroll
                for (int i = 0; i < 4; i++) {
                    int k = ch*8 + 2*i;
                    float f0 = fmaxf(fmaf(av, sgw[k],   sgw[64+k]),   0.f);
                    float f1 = fmaxf(fmaf(av, sgw[k+1], sgw[64+k+1]), 0.f);
                    __nv_bfloat162 b2 = __floats2bfloat162_rn(f0, f1);
                    w[i] = *reinterpret_cast<uint32_t*>(&b2);
                }
                sts128(sb + OFF_A + (uint32_t)((row*KP + ch*8)*2), make_uint4(w[0], w[1], w[2], w[3]));
            }
        } else {
            const __nv_bfloat16* src = d_y0b + (size_t)t*NNV*LH;
#pragma unroll
            for (int it = 0; it < 8; it++) {            // ih cols 0..127 via cp.async
                int idx = tid + it*128;
                int row = idx >> 4, ch = idx & 15;
                cp16(sb + OFF_A + (uint32_t)((row*KP + ch*8)*2), src + (size_t)(m0s + row)*LH + ch*8);
            }
            asm volatile("cp.async.commit_group;");
        }
    };
    auto issueB = [&](int ch, int bsel) {
        const __nv_bfloat16* src = img + ch*32*KP;
        uint32_t dst = sb + OFF_B + bsel*BCH;
        for (int i = tid; i < BCH/16; i += 128) cp16(dst + i*16, src + (size_t)i*8);
        asm volatile("cp.async.commit_group;");
    };

    stage_ih(0);
    issueB(0, 0);

    int buf = 0;
    for (int t = 0; t < T_STEPS; t++) {
        asm volatile("cp.async.wait_group 1;");
        __syncthreads();

        // A fragments for the whole step -> registers (32 rows/warp, 2 m16-groups)
        uint32_t afr[NK16][8];
        uint32_t aAddr0 = sb + OFF_A + (uint32_t)(((wr*32 + (g & 1)*8 + lr)*KP + (g >> 1)*8)*2);
#pragma unroll
        for (int s = 0; s < NK16; s++) {
            ldsm4(aAddr0 + s*32,                       afr[s][0], afr[s][1], afr[s][2], afr[s][3]);
            ldsm4(aAddr0 + (uint32_t)(16*KP*2) + s*32, afr[s][4], afr[s][5], afr[s][6], afr[s][7]);
        }
        __syncthreads();
        if (t + 1 < T_STEPS) stage_ih(t + 1);        // ih cols dead -> prefetch next step

        for (int ch = 0; ch < 16; ch++) {
            const bool last = (t == T_STEPS - 1 && ch == 15);
            if (!last) issueB((ch + 1) & 15, buf ^ 1);
            if (last) asm volatile("cp.async.wait_group 0;");
            else      asm volatile("cp.async.wait_group 1;");
            __syncthreads();

            float acc[2][2][4];
#pragma unroll
            for (int mt = 0; mt < 2; mt++)
#pragma unroll
                for (int nt = 0; nt < 2; nt++)
#pragma unroll
                    for (int i = 0; i < 4; i++) acc[mt][nt][i] = 0.f;

            // this warp's 16 cols within the 32-col chunk
            uint32_t bbase = sb + OFF_B + buf*BCH
                           + (uint32_t)(((wc*16 + (g >> 1)*8 + lr)*KP + (g & 1)*8)*2);
#pragma unroll
            for (int s = 0; s < NK16; s++) {
                uint32_t bB[4];
                ldsm4(bbase + s*32, bB[0], bB[1], bB[2], bB[3]);
                mma16816(acc[0][0], afr[s],     &bB[0]);
                mma16816(acc[0][1], afr[s],     &bB[2]);
                mma16816(acc[1][0], afr[s] + 4, &bB[0]);
                mma16816(acc[1][1], afr[s] + 4, &bB[2]);
            }

            // epilogue: in-register gate math via (i,f)/(g,o) pair shuffle
            {
                const bool evn = ((lane & 1) == 0);
#pragma unroll
                for (int mt = 0; mt < 2; mt++) {
                    const int rr = wr*32 + mt*16 + (lane >> 2) + (evn ? 0 : 8);
#pragma unroll
                    for (int nt = 0; nt < 2; nt++) {
                        float v1 = __shfl_xor_sync(0xffffffffu, evn ? acc[mt][nt][2] : acc[mt][nt][0], 1);
                        float v2 = __shfl_xor_sync(0xffffffffu, evn ? acc[mt][nt][3] : acc[mt][nt][1], 1);
                        float gi = evn ? acc[mt][nt][0] : v1;
                        float gf = evn ? acc[mt][nt][1] : v2;
                        float gg = evn ? v1 : acc[mt][nt][2];
                        float go = evn ? v2 : acc[mt][nt][3];
                        int uu = ch*8 + wc*4 + nt*2 + ((lane & 3) >> 1);
                        const float* b4 = sbias + uu*4;
                        gi += b4[0]; gf += b4[1]; gg += b4[2]; go += b4[3];
                        float cold = cS[rr*129 + uu];
                        float cn = sigmfast(gf)*cold + sigmfast(gi)*tanhfast(gg);
                        cS[rr*129 + uu] = cn;
                        float hv = sigmfast(go)*tanhfast(cn);
                        *(__nv_bfloat16*)(smem + OFF_A + (size_t)(rr*KP + KIH + uu)*2) = __float2bfloat16(hv);
                    }
                }
            }
            __syncthreads();
            buf ^= 1;
        }

        // coalesced h tile -> global (y0 for layer0; final h for layer1)
        if (LAYER == 0 || t == T_STEPS - 1) {
            __nv_bfloat16* dst = (LAYER == 0) ? (d_y0b + (size_t)t*NNV*LH) : d_hAb;
#pragma unroll
            for (int it = 0; it < 8; it++) {
                int idx = tid + it*128;
                int row = idx >> 4, c8 = idx & 15;
                uint4 v = *(uint4*)(smem + OFF_A + (size_t)(row*KP + KIH + c8*8)*2);
                *(uint4*)(dst + (size_t)(m0s + row)*LH + c8*8) = v;
            }
        }
    }
}

// ---------------- fused 2-layer LSTM: 250 CTAs x 64 rows, 2 CTAs/SM --------------
__global__ void __launch_bounds__(128, 2)
k_lstm_fused(const float* __restrict__ gw, const float* __restrict__ gb)
{
    extern __shared__ char smem[];
    const uint32_t sb = smem_u32(smem);
    const int m0s = blockIdx.x*64;

    run_layer<0>(smem, sb, gw, gb, m0s);
    __threadfence();          // y0 STG visible to layer-1 cp.async reads
    __syncthreads();
    run_layer<1>(smem, sb, gw, gb, m0s);
}

// ---------------- head: out = x_t + relu(h@pw1^T+pb1)@pw2^T + pb2 ----------------
__global__ void k_head(const __nv_bfloat16* __restrict__ h, const float* __restrict__ x,
                       const float* __restrict__ pw1, const float* __restrict__ pb1,
                       const float* __restrict__ pw2, const float* __restrict__ pb2,
                       float* __restrict__ out, int NN) {
    __shared__ float w1s[128][65];
    __shared__ float w2s[64], b1s[64];
    const int tid = threadIdx.x;
    for (int idx = tid; idx < 64*128; idx += 256) {
        int j = idx >> 7, k = idx & 127;
        w1s[k][j] = pw1[idx];
    }
    if (tid < 64) { w2s[tid] = pw2[tid]; b1s[tid] = pb1[tid]; }
    __syncthreads();

    int warp = tid >> 5, lane = tid & 31;
    int n = blockIdx.x*8 + warp;
    if (n >= NN) return;
    const __nv_bfloat16* hr = h + (size_t)n*LH;
    float s0 = b1s[lane], s1 = b1s[lane+32];
#pragma unroll 8
    for (int k = 0; k < 128; k++) {
        float hv = __bfloat162float(hr[k]);
        s0 = fmaf(hv, w1s[k][lane],    s0);
        s1 = fmaf(hv, w1s[k][lane+32], s1);
    }
    float part = fmaxf(s0, 0.f)*w2s[lane] + fmaxf(s1, 0.f)*w2s[lane+32];
#pragma unroll
    for (int o = 16; o; o >>= 1) part += __shfl_xor_sync(0xffffffffu, part, o);
    if (lane == 0) out[n] = part + pb2[0] + x[n*T_STEPS + (T_STEPS-1)];
}

// ---------------- launcher ----------------
extern "C" void kernel_launch(void* const* d_in, const int* in_sizes, int n_in,
                              void* d_out, int out_size) {
    const float* x    = (const float*)d_in[0];
    const int*   ei   = (const int*)  d_in[1];
    const float* gw   = (const float*)d_in[2];
    const float* gb   = (const float*)d_in[3];
    const float* wih0 = (const float*)d_in[4];
    const float* whh0 = (const float*)d_in[5];
    const float* bih0 = (const float*)d_in[6];
    const float* bhh0 = (const float*)d_in[7];
    const float* wih1 = (const float*)d_in[8];
    const float* whh1 = (const float*)d_in[9];
    const float* bih1 = (const float*)d_in[10];
    const float* bhh1 = (const float*)d_in[11];
    const float* pw1  = (const float*)d_in[12];
    const float* pb1  = (const float*)d_in[13];
    const float* pw2  = (const float*)d_in[14];
    const float* pb2  = (const float*)d_in[15];
    float* out = (float*)d_out;

    const int NN = in_sizes[0] / T_STEPS;   // 16000
    const int E  = in_sizes[1] / 2;         // 256000
    const int* src = ei;
    const int* dst = ei + E;

    float *p_deg, *p_dinv, *p_acc;
    __nv_bfloat16 *p_hAb;
    cudaGetSymbolAddress((void**)&p_deg,  d_deg);
    cudaGetSymbolAddress((void**)&p_dinv, d_dinv);
    cudaGetSymbolAddress((void**)&p_acc,  d_acc);
    cudaGetSymbolAddress((void**)&p_hAb,  d_hAb);

    cudaFuncSetAttribute(k_lstm_fused, cudaFuncAttributeMaxDynamicSharedMemorySize, SMB_TOT);

    // weight/bias images (+ deg-init), single launch
    k_prepw<<<(512*192 + 512*256 + 255)/256, 256>>>(wih0, whh0, wih1, whh1,
                                                    bih0, bhh0, bih1, bhh1, p_deg, NN);

    // GCN scalar aggregation
    k_deg_edges   <<<(E/4 + 255)/256, 256>>>(dst, p_deg, E);
    k_dinv_accinit<<<(NN  + 255)/256, 256>>>(x, p_deg, p_dinv, p_acc, NN);
    k_scatter     <<<(E/4 + 255)/256, 256>>>(src, dst, x, p_dinv, p_acc, E);

    // both LSTM layers, fused, 2 CTAs/SM
    k_lstm_fused<<<NCTA2, 128, SMB_TOT>>>(gw, gb);

    // head + residual
    k_head<<<(NN + 7)/8, 256>>>(p_hAb, x, pw1, pb1, pw2, pb2, out, NN);
}

// round 12
// speedup vs baseline: 1.0931x; 1.0931x over previous
#include <cuda_runtime.h>
#include <cuda_bf16.h>
#include <stdint.h>

#define T_STEPS 5
#define LH 128
#define NNV 16000
#define NCTA 125        // 16000/128

// ---------------- scratch (device globals; no runtime allocation) ----------------
__device__ float d_deg [NNV];
__device__ float d_dinv[NNV];
__device__ float d_acc [NNV*T_STEPS];
__device__ __nv_bfloat16 d_y0b [(size_t)T_STEPS*NNV*LH];   // layer-0 hidden sequence
__device__ __nv_bfloat16 d_hAb [(size_t)NNV*LH];           // final layer-1 h
__device__ __nv_bfloat16 d_img0[512*200];                  // layer0 weight image [j][k], pitch 200
__device__ __nv_bfloat16 d_img1[512*264];                  // layer1, pitch 264
__device__ float d_biasC[1024];                            // [layer][u*4+gate]

// ---------------- helpers ----------------
__device__ __forceinline__ float tanhfast(float x) {
    float y; asm("tanh.approx.f32 %0, %1;" : "=f"(y) : "f"(x)); return y;
}
__device__ __forceinline__ float sigmfast(float x) { return fmaf(tanhfast(0.5f*x), 0.5f, 0.5f); }

__device__ __forceinline__ uint32_t smem_u32(const void* p) {
    uint32_t a;
    asm("{ .reg .u64 t; cvta.to.shared.u64 t, %1; cvt.u32.u64 %0, t; }" : "=r"(a) : "l"(p));
    return a;
}
__device__ __forceinline__ void cp16(uint32_t d, const void* s) {
    asm volatile("cp.async.cg.shared.global [%0], [%1], 16;" :: "r"(d), "l"(s));
}
__device__ __forceinline__ void sts128(uint32_t a, uint4 v) {
    asm volatile("st.shared.v4.b32 [%0], {%1,%2,%3,%4};" :: "r"(a), "r"(v.x), "r"(v.y), "r"(v.z), "r"(v.w) : "memory");
}
__device__ __forceinline__ void ldsm4(uint32_t a, uint32_t& r0, uint32_t& r1, uint32_t& r2, uint32_t& r3) {
    asm volatile("ldmatrix.sync.aligned.m8n8.x4.shared.b16 {%0,%1,%2,%3}, [%4];"
                 : "=r"(r0), "=r"(r1), "=r"(r2), "=r"(r3) : "r"(a));
}
__device__ __forceinline__ void mma16816(float* d, const uint32_t* a, const uint32_t* b) {
    asm volatile("mma.sync.aligned.m16n8k16.row.col.f32.bf16.bf16.f32 "
        "{%0,%1,%2,%3}, {%4,%5,%6,%7}, {%8,%9}, {%0,%1,%2,%3};"
        : "+f"(d[0]), "+f"(d[1]), "+f"(d[2]), "+f"(d[3])
        : "r"(a[0]), "r"(a[1]), "r"(a[2]), "r"(a[3]), "r"(b[0]), "r"(b[1]));
}

// ---------------- GCN scalar pipeline (4-edge ILP) ----------------
__global__ void k_deg_edges(const int* __restrict__ dst, float* deg, int E) {
    int e0 = (blockIdx.x*blockDim.x + threadIdx.x)*4;
#pragma unroll
    for (int j = 0; j < 4; j++) {
        int e = e0 + j;
        if (e < E) atomicAdd(&deg[dst[e]], 1.0f);
    }
}
__global__ void k_dinv_accinit(const float* __restrict__ x, const float* __restrict__ deg,
                               float* __restrict__ dinv, float* __restrict__ acc, int n) {
    int i = blockIdx.x*blockDim.x + threadIdx.x;
    if (i >= n) return;
    float di = rsqrtf(deg[i]);
    dinv[i] = di;
#pragma unroll
    for (int t = 0; t < T_STEPS; t++)
        acc[i*T_STEPS + t] = x[i*T_STEPS + t] * di;
}
__global__ void k_scatter(const int* __restrict__ src, const int* __restrict__ dst,
                          const float* __restrict__ x, const float* __restrict__ dinv,
                          float* __restrict__ acc, int E) {
    int e0 = (blockIdx.x*blockDim.x + threadIdx.x)*4;
#pragma unroll
    for (int j = 0; j < 4; j++) {
        int e = e0 + j;
        if (e < E) {
            int s = src[e], d = dst[e];
            float ds = dinv[s];
#pragma unroll
            for (int t = 0; t < T_STEPS; t++)
                atomicAdd(&acc[d*T_STEPS + t], x[s*T_STEPS + t] * ds);
        }
    }
}

// ---------------- weight/bias pre-transform (both layers, one launch) ----------------
__global__ void k_prepw(const float* __restrict__ Wih0, const float* __restrict__ Whh0,
                        const float* __restrict__ Wih1, const float* __restrict__ Whh1,
                        const float* __restrict__ bi0, const float* __restrict__ bh0,
                        const float* __restrict__ bi1, const float* __restrict__ bh1,
                        float* deg, int nn) {
    int gid = blockIdx.x*256 + threadIdx.x;
    if (gid < nn) deg[gid] = 1.0f;
    if (gid < 1024) {
        int l = gid >> 9, r = gid & 511;
        int u = r >> 2, gt = r & 3;
        d_biasC[gid] = l ? (bi1[gt*LH + u] + bh1[gt*LH + u])
                         : (bi0[gt*LH + u] + bh0[gt*LH + u]);
    }
    const int W0 = 512*192;
    if (gid < W0) {
        int k = gid % 192, j = gid / 192;
        int u = j >> 2, gt = j & 3;
        float v = (k < 64) ? Wih0[(gt*LH + u)*64 + k] : Whh0[(gt*LH + u)*LH + (k - 64)];
        d_img0[j*200 + k] = __float2bfloat16(v);
    } else if (gid < W0 + 512*256) {
        int g2 = gid - W0;
        int k = g2 % 256, j = g2 / 256;
        int u = j >> 2, gt = j & 3;
        float v = (k < 128) ? Wih1[(gt*LH + u)*LH + k] : Whh1[(gt*LH + u)*LH + (k - 128)];
        d_img1[j*264 + k] = __float2bfloat16(v);
    }
}

// ---------------- one LSTM layer over this CTA's 128 rows (R10-proven tiling) -----
// 8 warps: 4 row-groups x 2 col-halves. B streamed in 64-col double-buffered
// chunks; A fragments register-resident per step; h lives in the A-tile
// h-columns; c in smem.
template<int LAYER>
__device__ __forceinline__ void run_layer(char* smem, uint32_t sb,
                                          const float* gw, const float* gb, int m0s)
{
    constexpr int KIH  = LAYER ? 128 : 64;
    constexpr int KP   = KIH + LH + 8;          // 264 / 200
    constexpr int NK16 = (KIH + LH) / 16;       // 16 / 12
    constexpr int AB   = 128*KP*2;
    constexpr int CB   = 128*129*4;
    constexpr int BCH  = 64*KP*2;
    constexpr int OFF_C    = AB;
    constexpr int OFF_B    = AB + CB;
    constexpr int OFF_BIAS = OFF_B + 2*BCH;
    constexpr int OFF_GW   = OFF_BIAS + 2048;

    float* cS    = (float*)(smem + OFF_C);      // [128][129]
    float* sbias = (float*)(smem + OFF_BIAS);   // 512
    float* sgw   = (float*)(smem + OFF_GW);     // 64 gw + 64 gb

    const int tid = threadIdx.x, wid = tid >> 5, lane = tid & 31;
    const int g = lane >> 3, lr = lane & 7;
    const int wr = wid >> 1, wc = wid & 1;      // 4 row-groups x 2 col-halves
    const __nv_bfloat16* img = LAYER ? d_img1 : d_img0;

    if (LAYER == 0 && tid < 128) sgw[tid] = (tid < 64) ? gw[tid] : gb[tid - 64];
    for (int i = tid; i < 512; i += 256) sbias[i] = d_biasC[LAYER*512 + i];
    // zero A tile (h cols = h0 = 0) and c
    for (int i = tid; i < AB/16; i += 256) ((uint4*)smem)[i] = make_uint4(0,0,0,0);
    for (int i = tid; i < CB/16; i += 256) ((uint4*)(smem + OFF_C))[i] = make_uint4(0,0,0,0);
    __syncthreads();

    auto stage_ih = [&](int t) {
        if (LAYER == 0) {
#pragma unroll
            for (int it = 0; it < 4; it++) {            // feat cols 0..63 in-register
                int idx = tid + it*256;
                int row = idx >> 3, ch = idx & 7;
                int m = m0s + row;
                float av = d_acc[m*T_STEPS + t] * d_dinv[m];
                uint32_t w[4];
#pragma unroll
                for (int i = 0; i < 4; i++) {
                    int k = ch*8 + 2*i;
                    float f0 = fmaxf(fmaf(av, sgw[k],   sgw[64+k]),   0.f);
                    float f1 = fmaxf(fmaf(av, sgw[k+1], sgw[64+k+1]), 0.f);
                    __nv_bfloat162 b2 = __floats2bfloat162_rn(f0, f1);
                    w[i] = *reinterpret_cast<uint32_t*>(&b2);
                }
                sts128(sb + (uint32_t)((row*KP + ch*8)*2), make_uint4(w[0], w[1], w[2], w[3]));
            }
        } else {
            const __nv_bfloat16* src = d_y0b + (size_t)t*NNV*LH;
#pragma unroll
            for (int it = 0; it < 8; it++) {            // ih cols 0..127 via cp.async
                int idx = tid + it*256;
                int row = idx >> 4, ch = idx & 15;
                cp16(sb + (uint32_t)((row*KP + ch*8)*2), src + (size_t)(m0s + row)*LH + ch*8);
            }
            asm volatile("cp.async.commit_group;");
        }
    };
    auto issueB = [&](int ch, int bsel) {
        const __nv_bfloat16* src = img + ch*64*KP;
        uint32_t dst = sb + OFF_B + bsel*BCH;
        for (int i = tid; i < BCH/16; i += 256) cp16(dst + i*16, src + (size_t)i*8);
        asm volatile("cp.async.commit_group;");
    };

    stage_ih(0);
    issueB(0, 0);

    int buf = 0;
    for (int t = 0; t < T_STEPS; t++) {
        asm volatile("cp.async.wait_group 1;");      // ih for this step done
        __syncthreads();                             // h-col epilogue writes visible

        // A fragments for the whole step -> registers (32 rows/warp, 2 m16-groups)
        uint32_t afr[NK16][8];
        uint32_t aAddr0 = sb + (uint32_t)(((wr*32 + (g & 1)*8 + lr)*KP + (g >> 1)*8)*2);
#pragma unroll
        for (int s = 0; s < NK16; s++) {
            ldsm4(aAddr0 + s*32,                       afr[s][0], afr[s][1], afr[s][2], afr[s][3]);
            ldsm4(aAddr0 + (uint32_t)(16*KP*2) + s*32, afr[s][4], afr[s][5], afr[s][6], afr[s][7]);
        }
        __syncthreads();
        if (t + 1 < T_STEPS) stage_ih(t + 1);        // ih cols dead -> prefetch next step

        for (int ch = 0; ch < 8; ch++) {
            const bool last = (t == T_STEPS - 1 && ch == 7);
            if (!last) issueB((ch + 1) & 7, buf ^ 1);
            if (last) asm volatile("cp.async.wait_group 0;");   // race fix: needed group must land
            else      asm volatile("cp.async.wait_group 1;");
            __syncthreads();

            float acc[2][4][4];
#pragma unroll
            for (int mt = 0; mt < 2; mt++)
#pragma unroll
                for (int nt = 0; nt < 4; nt++)
#pragma unroll
                    for (int i = 0; i < 4; i++) acc[mt][nt][i] = 0.f;

            // this warp's 32 cols within the 64-col chunk
            uint32_t bbase = sb + OFF_B + buf*BCH
                           + (uint32_t)(((wc*32 + (g >> 1)*8 + lr)*KP + (g & 1)*8)*2);
#pragma unroll
            for (int s = 0; s < NK16; s++) {
                uint32_t bB[2][4];
#pragma unroll
                for (int p = 0; p < 2; p++)
                    ldsm4(bbase + (uint32_t)(p*16*KP*2) + s*32, bB[p][0], bB[p][1], bB[p][2], bB[p][3]);
#pragma unroll
                for (int p = 0; p < 2; p++) {
                    mma16816(acc[0][2*p],   afr[s],     &bB[p][0]);
                    mma16816(acc[0][2*p+1], afr[s],     &bB[p][2]);
                    mma16816(acc[1][2*p],   afr[s] + 4, &bB[p][0]);
                    mma16816(acc[1][2*p+1], afr[s] + 4, &bB[p][2]);
                }
            }

            // epilogue: in-register gate math via (i,f)/(g,o) pair shuffle
            {
                const bool evn = ((lane & 1) == 0);
#pragma unroll
                for (int mt = 0; mt < 2; mt++) {
                    const int rr = wr*32 + mt*16 + (lane >> 2) + (evn ? 0 : 8);
#pragma unroll
                    for (int nt = 0; nt < 4; nt++) {
                        float v1 = __shfl_xor_sync(0xffffffffu, evn ? acc[mt][nt][2] : acc[mt][nt][0], 1);
                        float v2 = __shfl_xor_sync(0xffffffffu, evn ? acc[mt][nt][3] : acc[mt][nt][1], 1);
                        float gi = evn ? acc[mt][nt][0] : v1;
                        float gf = evn ? acc[mt][nt][1] : v2;
                        float gg = evn ? v1 : acc[mt][nt][2];
                        float go = evn ? v2 : acc[mt][nt][3];
                        int uu = ch*16 + wc*8 + nt*2 + ((lane & 3) >> 1);
                        const float* b4 = sbias + uu*4;
                        gi += b4[0]; gf += b4[1]; gg += b4[2]; go += b4[3];
                        float cold = cS[rr*129 + uu];
                        float cn = sigmfast(gf)*cold + sigmfast(gi)*tanhfast(gg);
                        cS[rr*129 + uu] = cn;
                        float hv = sigmfast(go)*tanhfast(cn);
                        *(__nv_bfloat16*)(smem + (size_t)(rr*KP + KIH + uu)*2) = __float2bfloat16(hv);
                    }
                }
            }
            __syncthreads();
            buf ^= 1;
        }

        // coalesced h tile -> global (y0 for layer0; final h for layer1)
        if (LAYER == 0 || t == T_STEPS - 1) {
            __nv_bfloat16* dst = (LAYER == 0) ? (d_y0b + (size_t)t*NNV*LH) : d_hAb;
#pragma unroll
            for (int it = 0; it < 8; it++) {
                int idx = tid + it*256;
                int row = idx >> 4, c8 = idx & 15;
                uint4 v = *(uint4*)(smem + (size_t)(row*KP + KIH + c8*8)*2);
                *(uint4*)(dst + (size_t)(m0s + row)*LH + c8*8) = v;
            }
        }
    }
}

// ---------------- fused 2-layer LSTM: 125 CTAs x 128 rows -------------------------
__global__ void __launch_bounds__(256, 1)
k_lstm_fused(const float* __restrict__ gw, const float* __restrict__ gb)
{
    extern __shared__ char smem[];
    const uint32_t sb = smem_u32(smem);
    const int m0s = blockIdx.x*128;

    run_layer<0>(smem, sb, gw, gb, m0s);
    __threadfence();          // y0 STG visible to layer-1 cp.async reads
    __syncthreads();          // all warps done with layer-0 smem before re-zero
    run_layer<1>(smem, sb, gw, gb, m0s);
}

// ---------------- head: out = x_t + relu(h@pw1^T+pb1)@pw2^T + pb2 ----------------
__global__ void k_head(const __nv_bfloat16* __restrict__ h, const float* __restrict__ x,
                       const float* __restrict__ pw1, const float* __restrict__ pb1,
                       const float* __restrict__ pw2, const float* __restrict__ pb2,
                       float* __restrict__ out, int NN) {
    __shared__ float w1s[128][65];
    __shared__ float w2s[64], b1s[64];
    const int tid = threadIdx.x;
    for (int idx = tid; idx < 64*128; idx += 256) {
        int j = idx >> 7, k = idx & 127;
        w1s[k][j] = pw1[idx];
    }
    if (tid < 64) { w2s[tid] = pw2[tid]; b1s[tid] = pb1[tid]; }
    __syncthreads();

    int warp = tid >> 5, lane = tid & 31;
    int n = blockIdx.x*8 + warp;
    if (n >= NN) return;
    const __nv_bfloat16* hr = h + (size_t)n*LH;
    float s0 = b1s[lane], s1 = b1s[lane+32];
#pragma unroll 8
    for (int k = 0; k < 128; k++) {
        float hv = __bfloat162float(hr[k]);
        s0 = fmaf(hv, w1s[k][lane],    s0);
        s1 = fmaf(hv, w1s[k][lane+32], s1);
    }
    float part = fmaxf(s0, 0.f)*w2s[lane] + fmaxf(s1, 0.f)*w2s[lane+32];
#pragma unroll
    for (int o = 16; o; o >>= 1) part += __shfl_xor_sync(0xffffffffu, part, o);
    if (lane == 0) out[n] = part + pb2[0] + x[n*T_STEPS + (T_STEPS-1)];
}

// ---------------- launcher ----------------
extern "C" void kernel_launch(void* const* d_in, const int* in_sizes, int n_in,
                              void* d_out, int out_size) {
    const float* x    = (const float*)d_in[0];
    const int*   ei   = (const int*)  d_in[1];
    const float* gw   = (const float*)d_in[2];
    const float* gb   = (const float*)d_in[3];
    const float* wih0 = (const float*)d_in[4];
    const float* whh0 = (const float*)d_in[5];
    const float* bih0 = (const float*)d_in[6];
    const float* bhh0 = (const float*)d_in[7];
    const float* wih1 = (const float*)d_in[8];
    const float* whh1 = (const float*)d_in[9];
    const float* bih1 = (const float*)d_in[10];
    const float* bhh1 = (const float*)d_in[11];
    const float* pw1  = (const float*)d_in[12];
    const float* pb1  = (const float*)d_in[13];
    const float* pw2  = (const float*)d_in[14];
    const float* pb2  = (const float*)d_in[15];
    float* out = (float*)d_out;

    const int NN = in_sizes[0] / T_STEPS;   // 16000
    const int E  = in_sizes[1] / 2;         // 256000
    const int* src = ei;
    const int* dst = ei + E;

    float *p_deg, *p_dinv, *p_acc;
    __nv_bfloat16 *p_hAb;
    cudaGetSymbolAddress((void**)&p_deg,  d_deg);
    cudaGetSymbolAddress((void**)&p_dinv, d_dinv);
    cudaGetSymbolAddress((void**)&p_acc,  d_acc);
    cudaGetSymbolAddress((void**)&p_hAb,  d_hAb);

    // dynamic smem sized for layer1 (worst case): A + c + 2*Bchunk + bias + gwgb
    const int SMB = 128*264*2 + 128*129*4 + 2*64*264*2 + 2048 + 512;   // 203776
    cudaFuncSetAttribute(k_lstm_fused, cudaFuncAttributeMaxDynamicSharedMemorySize, SMB);

    // weight/bias images (+ deg-init), single launch
    k_prepw<<<(512*192 + 512*256 + 255)/256, 256>>>(wih0, whh0, wih1, whh1,
                                                    bih0, bhh0, bih1, bhh1, p_deg, NN);

    // GCN scalar aggregation
    k_deg_edges   <<<(E/4 + 255)/256, 256>>>(dst, p_deg, E);
    k_dinv_accinit<<<(NN  + 255)/256, 256>>>(x, p_deg, p_dinv, p_acc, NN);
    k_scatter     <<<(E/4 + 255)/256, 256>>>(src, dst, x, p_dinv, p_acc, E);

    // both LSTM layers, fused, R10 tiling
    k_lstm_fused<<<NCTA, 256, SMB>>>(gw, gb);

    // head + residual
    k_head<<<(NN + 7)/8, 256>>>(p_hAb, x, pw1, pb1, pw2, pb2, out, NN);
}

// round 13
// speedup vs baseline: 1.1245x; 1.0288x over previous
#include <cuda_runtime.h>
#include <cuda_bf16.h>
#include <stdint.h>

#define T_STEPS 5
#define LH 128
#define NNV 16000
#define NCTA 125        // 16000/128

// ---------------- scratch (device globals; no runtime allocation) ----------------
__device__ float d_deg [NNV];                              // self-zeroing edge counts
__device__ float d_dinv[NNV];
__device__ float d_acc [NNV*T_STEPS];
__device__ __nv_bfloat16 d_y0b [(size_t)T_STEPS*NNV*LH];   // layer-0 hidden sequence
__device__ __nv_bfloat16 d_img0[512*200];                  // layer0 weight image [j][k], pitch 200
__device__ __nv_bfloat16 d_img1[512*264];                  // layer1, pitch 264
__device__ float d_biasC[1024];                            // [layer][u*4+gate]

// ---------------- helpers ----------------
__device__ __forceinline__ float tanhfast(float x) {
    float y; asm("tanh.approx.f32 %0, %1;" : "=f"(y) : "f"(x)); return y;
}
__device__ __forceinline__ float sigmfast(float x) { return fmaf(tanhfast(0.5f*x), 0.5f, 0.5f); }

__device__ __forceinline__ uint32_t smem_u32(const void* p) {
    uint32_t a;
    asm("{ .reg .u64 t; cvta.to.shared.u64 t, %1; cvt.u32.u64 %0, t; }" : "=r"(a) : "l"(p));
    return a;
}
__device__ __forceinline__ void cp16(uint32_t d, const void* s) {
    asm volatile("cp.async.cg.shared.global [%0], [%1], 16;" :: "r"(d), "l"(s));
}
__device__ __forceinline__ void sts128(uint32_t a, uint4 v) {
    asm volatile("st.shared.v4.b32 [%0], {%1,%2,%3,%4};" :: "r"(a), "r"(v.x), "r"(v.y), "r"(v.z), "r"(v.w) : "memory");
}
__device__ __forceinline__ void ldsm4(uint32_t a, uint32_t& r0, uint32_t& r1, uint32_t& r2, uint32_t& r3) {
    asm volatile("ldmatrix.sync.aligned.m8n8.x4.shared.b16 {%0,%1,%2,%3}, [%4];"
                 : "=r"(r0), "=r"(r1), "=r"(r2), "=r"(r3) : "r"(a));
}
__device__ __forceinline__ void mma16816(float* d, const uint32_t* a, const uint32_t* b) {
    asm volatile("mma.sync.aligned.m16n8k16.row.col.f32.bf16.bf16.f32 "
        "{%0,%1,%2,%3}, {%4,%5,%6,%7}, {%8,%9}, {%0,%1,%2,%3};"
        : "+f"(d[0]), "+f"(d[1]), "+f"(d[2]), "+f"(d[3])
        : "r"(a[0]), "r"(a[1]), "r"(a[2]), "r"(a[3]), "r"(b[0]), "r"(b[1]));
}

// ---------------- prep: weight/bias images + edge-degree counting, ONE launch -----
// deg starts at 0 (zero-init / self-zeroed by k_dinv_accinit each call); self-loop
// is folded in later as rsqrtf(cnt + 1).
__global__ void k_prep(const float* __restrict__ Wih0, const float* __restrict__ Whh0,
                       const float* __restrict__ Wih1, const float* __restrict__ Whh1,
                       const float* __restrict__ bi0, const float* __restrict__ bh0,
                       const float* __restrict__ bi1, const float* __restrict__ bh1,
                       const int* __restrict__ dst, int E) {
    int gid = blockIdx.x*256 + threadIdx.x;

    // edge-degree counting (4-edge ILP)
    int e0 = gid*4;
#pragma unroll
    for (int j = 0; j < 4; j++) {
        int e = e0 + j;
        if (e < E) atomicAdd(&d_deg[dst[e]], 1.0f);
    }

    // combined biases
    if (gid < 1024) {
        int l = gid >> 9, r = gid & 511;
        int u = r >> 2, gt = r & 3;
        d_biasC[gid] = l ? (bi1[gt*LH + u] + bh1[gt*LH + u])
                         : (bi0[gt*LH + u] + bh0[gt*LH + u]);
    }

    // weight images: img[j][k], j = 4*unit + gate, k = [ih | hh]
    const int W0 = 512*192;
    if (gid < W0) {
        int k = gid % 192, j = gid / 192;
        int u = j >> 2, gt = j & 3;
        float v = (k < 64) ? Wih0[(gt*LH + u)*64 + k] : Whh0[(gt*LH + u)*LH + (k - 64)];
        d_img0[j*200 + k] = __float2bfloat16(v);
    } else if (gid < W0 + 512*256) {
        int g2 = gid - W0;
        int k = g2 % 256, j = g2 / 256;
        int u = j >> 2, gt = j & 3;
        float v = (k < 128) ? Wih1[(gt*LH + u)*LH + k] : Whh1[(gt*LH + u)*LH + (k - 128)];
        d_img1[j*264 + k] = __float2bfloat16(v);
    }
}

__global__ void k_dinv_accinit(const float* __restrict__ x, float* __restrict__ deg,
                               float* __restrict__ dinv, float* __restrict__ acc, int n) {
    int i = blockIdx.x*blockDim.x + threadIdx.x;
    if (i >= n) return;
    float di = rsqrtf(deg[i] + 1.0f);     // +1 = self-loop
    deg[i] = 0.f;                         // re-zero for next graph replay
    dinv[i] = di;
#pragma unroll
    for (int t = 0; t < T_STEPS; t++)
        acc[i*T_STEPS + t] = x[i*T_STEPS + t] * di;
}
__global__ void k_scatter(const int* __restrict__ src, const int* __restrict__ dst,
                          const float* __restrict__ x, const float* __restrict__ dinv,
                          float* __restrict__ acc, int E) {
    int e0 = (blockIdx.x*blockDim.x + threadIdx.x)*4;
#pragma unroll
    for (int j = 0; j < 4; j++) {
        int e = e0 + j;
        if (e < E) {
            int s = src[e], d = dst[e];
            float ds = dinv[s];
#pragma unroll
            for (int t = 0; t < T_STEPS; t++)
                atomicAdd(&acc[d*T_STEPS + t], x[s*T_STEPS + t] * ds);
        }
    }
}

// ---------------- one LSTM layer over this CTA's 128 rows (R10/R12-proven tiling) --
template<int LAYER>
__device__ __forceinline__ void run_layer(char* smem, uint32_t sb,
                                          const float* gw, const float* gb, int m0s)
{
    constexpr int KIH  = LAYER ? 128 : 64;
    constexpr int KP   = KIH + LH + 8;          // 264 / 200
    constexpr int NK16 = (KIH + LH) / 16;       // 16 / 12
    constexpr int AB   = 128*KP*2;
    constexpr int CB   = 128*129*4;
    constexpr int BCH  = 64*KP*2;
    constexpr int OFF_C    = AB;
    constexpr int OFF_B    = AB + CB;
    constexpr int OFF_BIAS = OFF_B + 2*BCH;
    constexpr int OFF_GW   = OFF_BIAS + 2048;

    float* cS    = (float*)(smem + OFF_C);      // [128][129]
    float* sbias = (float*)(smem + OFF_BIAS);   // 512
    float* sgw   = (float*)(smem + OFF_GW);     // 64 gw + 64 gb

    const int tid = threadIdx.x, wid = tid >> 5, lane = tid & 31;
    const int g = lane >> 3, lr = lane & 7;
    const int wr = wid >> 1, wc = wid & 1;      // 4 row-groups x 2 col-halves
    const __nv_bfloat16* img = LAYER ? d_img1 : d_img0;

    if (LAYER == 0 && tid < 128) sgw[tid] = (tid < 64) ? gw[tid] : gb[tid - 64];
    for (int i = tid; i < 512; i += 256) sbias[i] = d_biasC[LAYER*512 + i];
    // zero A tile (h cols = h0 = 0) and c
    for (int i = tid; i < AB/16; i += 256) ((uint4*)smem)[i] = make_uint4(0,0,0,0);
    for (int i = tid; i < CB/16; i += 256) ((uint4*)(smem + OFF_C))[i] = make_uint4(0,0,0,0);
    __syncthreads();

    auto stage_ih = [&](int t) {
        if (LAYER == 0) {
#pragma unroll
            for (int it = 0; it < 4; it++) {            // feat cols 0..63 in-register
                int idx = tid + it*256;
                int row = idx >> 3, ch = idx & 7;
                int m = m0s + row;
                float av = d_acc[m*T_STEPS + t] * d_dinv[m];
                uint32_t w[4];
#pragma unroll
                for (int i = 0; i < 4; i++) {
                    int k = ch*8 + 2*i;
                    float f0 = fmaxf(fmaf(av, sgw[k],   sgw[64+k]),   0.f);
                    float f1 = fmaxf(fmaf(av, sgw[k+1], sgw[64+k+1]), 0.f);
                    __nv_bfloat162 b2 = __floats2bfloat162_rn(f0, f1);
                    w[i] = *reinterpret_cast<uint32_t*>(&b2);
                }
                sts128(sb + (uint32_t)((row*KP + ch*8)*2), make_uint4(w[0], w[1], w[2], w[3]));
            }
        } else {
            const __nv_bfloat16* src = d_y0b + (size_t)t*NNV*LH;
#pragma unroll
            for (int it = 0; it < 8; it++) {            // ih cols 0..127 via cp.async
                int idx = tid + it*256;
                int row = idx >> 4, ch = idx & 15;
                cp16(sb + (uint32_t)((row*KP + ch*8)*2), src + (size_t)(m0s + row)*LH + ch*8);
            }
            asm volatile("cp.async.commit_group;");
        }
    };
    auto issueB = [&](int ch, int bsel) {
        const __nv_bfloat16* src = img + ch*64*KP;
        uint32_t dst = sb + OFF_B + bsel*BCH;
        for (int i = tid; i < BCH/16; i += 256) cp16(dst + i*16, src + (size_t)i*8);
        asm volatile("cp.async.commit_group;");
    };

    stage_ih(0);
    issueB(0, 0);

    int buf = 0;
    for (int t = 0; t < T_STEPS; t++) {
        asm volatile("cp.async.wait_group 1;");      // ih for this step done
        __syncthreads();                             // h-col epilogue writes visible

        // A fragments for the whole step -> registers (32 rows/warp, 2 m16-groups)
        uint32_t afr[NK16][8];
        uint32_t aAddr0 = sb + (uint32_t)(((wr*32 + (g & 1)*8 + lr)*KP + (g >> 1)*8)*2);
#pragma unroll
        for (int s = 0; s < NK16; s++) {
            ldsm4(aAddr0 + s*32,                       afr[s][0], afr[s][1], afr[s][2], afr[s][3]);
            ldsm4(aAddr0 + (uint32_t)(16*KP*2) + s*32, afr[s][4], afr[s][5], afr[s][6], afr[s][7]);
        }
        __syncthreads();
        if (t + 1 < T_STEPS) stage_ih(t + 1);        // ih cols dead -> prefetch next step

        for (int ch = 0; ch < 8; ch++) {
            const bool last = (t == T_STEPS - 1 && ch == 7);
            if (!last) issueB((ch + 1) & 7, buf ^ 1);
            if (last) asm volatile("cp.async.wait_group 0;");
            else      asm volatile("cp.async.wait_group 1;");
            __syncthreads();

            float acc[2][4][4];
#pragma unroll
            for (int mt = 0; mt < 2; mt++)
#pragma unroll
                for (int nt = 0; nt < 4; nt++)
#pragma unroll
                    for (int i = 0; i < 4; i++) acc[mt][nt][i] = 0.f;

            // this warp's 32 cols within the 64-col chunk
            uint32_t bbase = sb + OFF_B + buf*BCH
                           + (uint32_t)(((wc*32 + (g >> 1)*8 + lr)*KP + (g & 1)*8)*2);
#pragma unroll
            for (int s = 0; s < NK16; s++) {
                uint32_t bB[2][4];
#pragma unroll
                for (int p = 0; p < 2; p++)
                    ldsm4(bbase + (uint32_t)(p*16*KP*2) + s*32, bB[p][0], bB[p][1], bB[p][2], bB[p][3]);
#pragma unroll
                for (int p = 0; p < 2; p++) {
                    mma16816(acc[0][2*p],   afr[s],     &bB[p][0]);
                    mma16816(acc[0][2*p+1], afr[s],     &bB[p][2]);
                    mma16816(acc[1][2*p],   afr[s] + 4, &bB[p][0]);
                    mma16816(acc[1][2*p+1], afr[s] + 4, &bB[p][2]);
                }
            }

            // epilogue: in-register gate math via (i,f)/(g,o) pair shuffle
            {
                const bool evn = ((lane & 1) == 0);
#pragma unroll
                for (int mt = 0; mt < 2; mt++) {
                    const int rr = wr*32 + mt*16 + (lane >> 2) + (evn ? 0 : 8);
#pragma unroll
                    for (int nt = 0; nt < 4; nt++) {
                        float v1 = __shfl_xor_sync(0xffffffffu, evn ? acc[mt][nt][2] : acc[mt][nt][0], 1);
                        float v2 = __shfl_xor_sync(0xffffffffu, evn ? acc[mt][nt][3] : acc[mt][nt][1], 1);
                        float gi = evn ? acc[mt][nt][0] : v1;
                        float gf = evn ? acc[mt][nt][1] : v2;
                        float gg = evn ? v1 : acc[mt][nt][2];
                        float go = evn ? v2 : acc[mt][nt][3];
                        int uu = ch*16 + wc*8 + nt*2 + ((lane & 3) >> 1);
                        const float* b4 = sbias + uu*4;
                        gi += b4[0]; gf += b4[1]; gg += b4[2]; go += b4[3];
                        float cold = cS[rr*129 + uu];
                        float cn = sigmfast(gf)*cold + sigmfast(gi)*tanhfast(gg);
                        cS[rr*129 + uu] = cn;
                        float hv = sigmfast(go)*tanhfast(cn);
                        *(__nv_bfloat16*)(smem + (size_t)(rr*KP + KIH + uu)*2) = __float2bfloat16(hv);
                    }
                }
            }
            __syncthreads();
            buf ^= 1;
        }

        // layer0: h tile -> global y0 (layer1 final h stays in smem for the fused head)
        if (LAYER == 0) {
            __nv_bfloat16* dst = d_y0b + (size_t)t*NNV*LH;
#pragma unroll
            for (int it = 0; it < 8; it++) {
                int idx = tid + it*256;
                int row = idx >> 4, c8 = idx & 15;
                uint4 v = *(uint4*)(smem + (size_t)(row*KP + KIH + c8*8)*2);
                *(uint4*)(dst + (size_t)(m0s + row)*LH + c8*8) = v;
            }
        }
    }
}

// ---------------- fused 2-layer LSTM + head: 125 CTAs x 128 rows -------------------
__global__ void __launch_bounds__(256, 1)
k_lstm_fused(const float* __restrict__ gw, const float* __restrict__ gb,
             const float* __restrict__ x,
             const float* __restrict__ pw1, const float* __restrict__ pb1,
             const float* __restrict__ pw2, const float* __restrict__ pb2,
             float* __restrict__ out)
{
    extern __shared__ char smem[];
    const uint32_t sb = smem_u32(smem);
    const int m0s = blockIdx.x*128;
    const int tid = threadIdx.x, wid = tid >> 5, lane = tid & 31;

    run_layer<0>(smem, sb, gw, gb, m0s);
    __threadfence();          // y0 STG visible to layer-1 cp.async reads
    __syncthreads();
    run_layer<1>(smem, sb, gw, gb, m0s);

    // ---- fused head: final h is in the layer-1 A-tile h-columns (bf16, smem) ----
    // out[m] = x[m,T-1] + relu(h @ pw1^T + pb1) @ pw2^T + pb2
    constexpr int KP1 = 264, KIH1 = 128;
    constexpr int OFF_HB = 128*KP1*2 + 128*129*4;            // dead B-buffer region
    float* w1s = (float*)(smem + OFF_HB);                    // [128][65]
    float* w2s = (float*)(smem + OFF_HB + 128*65*4);         // 64
    float* b1s = w2s + 64;                                   // 64

    // last epilogue __syncthreads already passed; B region is dead
    for (int idx = tid; idx < 64*128; idx += 256) {          // pw1 (64,128) -> [k][j]
        int j = idx >> 7, k = idx & 127;
        w1s[k*65 + j] = pw1[idx];
    }
    if (tid < 64) { w2s[tid] = pw2[tid]; b1s[tid] = pb1[tid]; }
    __syncthreads();

    const float pb2v = pb2[0];
#pragma unroll 1
    for (int r = 0; r < 16; r++) {                           // each warp: 16 rows
        int row = wid*16 + r;
        int m = m0s + row;
        const char* hrow = smem + (size_t)(row*KP1 + KIH1)*2;
        float s0 = b1s[lane], s1 = b1s[lane + 32];
#pragma unroll
        for (int k4 = 0; k4 < 32; k4++) {                    // 4 h values per iter
            uint2 hv = *(const uint2*)(hrow + k4*8);
            __nv_bfloat162 h01 = *reinterpret_cast<__nv_bfloat162*>(&hv.x);
            __nv_bfloat162 h23 = *reinterpret_cast<__nv_bfloat162*>(&hv.y);
            float f0 = __bfloat162float(h01.x), f1 = __bfloat162float(h01.y);
            float f2 = __bfloat162float(h23.x), f3 = __bfloat162float(h23.y);
            const float* wk = w1s + (k4*4)*65;
            s0 = fmaf(f0, wk[lane],        s0);
            s1 = fmaf(f0, wk[lane+32],     s1);
            s0 = fmaf(f1, wk[65+lane],     s0);
            s1 = fmaf(f1, wk[65+lane+32],  s1);
            s0 = fmaf(f2, wk[130+lane],    s0);
            s1 = fmaf(f2, wk[130+lane+32], s1);
            s0 = fmaf(f3, wk[195+lane],    s0);
            s1 = fmaf(f3, wk[195+lane+32], s1);
        }
        float part = fmaxf(s0, 0.f)*w2s[lane] + fmaxf(s1, 0.f)*w2s[lane+32];
#pragma unroll
        for (int o = 16; o; o >>= 1) part += __shfl_xor_sync(0xffffffffu, part, o);
        if (lane == 0) out[m] = part + pb2v + x[m*T_STEPS + (T_STEPS-1)];
    }
}

// ---------------- launcher ----------------
extern "C" void kernel_launch(void* const* d_in, const int* in_sizes, int n_in,
                              void* d_out, int out_size) {
    const float* x    = (const float*)d_in[0];
    const int*   ei   = (const int*)  d_in[1];
    const float* gw   = (const float*)d_in[2];
    const float* gb   = (const float*)d_in[3];
    const float* wih0 = (const float*)d_in[4];
    const float* whh0 = (const float*)d_in[5];
    const float* bih0 = (const float*)d_in[6];
    const float* bhh0 = (const float*)d_in[7];
    const float* wih1 = (const float*)d_in[8];
    const float* whh1 = (const float*)d_in[9];
    const float* bih1 = (const float*)d_in[10];
    const float* bhh1 = (const float*)d_in[11];
    const float* pw1  = (const float*)d_in[12];
    const float* pb1  = (const float*)d_in[13];
    const float* pw2  = (const float*)d_in[14];
    const float* pb2  = (const float*)d_in[15];
    float* out = (float*)d_out;

    const int NN = in_sizes[0] / T_STEPS;   // 16000
    const int E  = in_sizes[1] / 2;         // 256000
    const int* src = ei;
    const int* dst = ei + E;

    float *p_deg, *p_dinv, *p_acc;
    cudaGetSymbolAddress((void**)&p_deg,  d_deg);
    cudaGetSymbolAddress((void**)&p_dinv, d_dinv);
    cudaGetSymbolAddress((void**)&p_acc,  d_acc);

    // dynamic smem sized for layer1 (worst case): A + c + 2*Bchunk + bias + gwgb
    const int SMB = 128*264*2 + 128*129*4 + 2*64*264*2 + 2048 + 512;   // 203776
    cudaFuncSetAttribute(k_lstm_fused, cudaFuncAttributeMaxDynamicSharedMemorySize, SMB);

    // prep (weights + biases + edge-degree counting), single launch
    const int prepThreads = 512*192 + 512*256;               // dominates E/4 and 1024
    k_prep<<<(prepThreads + 255)/256, 256>>>(wih0, whh0, wih1, whh1,
                                             bih0, bhh0, bih1, bhh1, dst, E);

    // GCN scalar aggregation
    k_dinv_accinit<<<(NN  + 255)/256, 256>>>(x, p_deg, p_dinv, p_acc, NN);
    k_scatter     <<<(E/4 + 255)/256, 256>>>(src, dst, x, p_dinv, p_acc, E);

    // both LSTM layers + head, fused
    k_lstm_fused<<<NCTA, 256, SMB>>>(gw, gb, x, pw1, pb1, pw2, pb2, out);
}